// round 4
// baseline (speedup 1.0000x reference)
#include <cuda_runtime.h>

#define NUM_CLASSES 23
#define HW (512*512)               // 262144 = 2^18
#define HW_SHIFT 18
#define NPIX (8*HW)                // 2097152
#define NPAIR (NPIX/2)             // 1048576
#define GRID 296
#define BLOCK 256
#define NWARPS (BLOCK/32)
#define NVALS (2*NUM_CLASSES + 1)  // 47
#define SMOOTH 1e-5f
#define LOG2E 1.4426950408889634f
#define LN2   0.6931471805599453f

__device__ float g_scratch[NVALS * GRID];
__device__ unsigned int g_count;   // zero-init; self-resetting each launch

__device__ __forceinline__ float warp_sum(float v) {
    #pragma unroll
    for (int off = 16; off; off >>= 1)
        v += __shfl_down_sync(0xffffffffu, v, off);
    return v;
}

// Raw MUFU ops (independent of --use_fast_math)
__device__ __forceinline__ float fex2(float x) {
    float y; asm("ex2.approx.f32 %0, %1;" : "=f"(y) : "f"(x)); return y;
}
__device__ __forceinline__ float flg2(float x) {
    float y; asm("lg2.approx.f32 %0, %1;" : "=f"(y) : "f"(x)); return y;
}
__device__ __forceinline__ float frcp(float x) {
    float y; asm("rcp.approx.f32 %0, %1;" : "=f"(y) : "f"(x)); return y;
}

// Blackwell packed fp32x2 ops (PTX-only; halves FMA-pipe instruction count)
__device__ __forceinline__ float2 f32x2_mul(float2 a, float2 b) {
    unsigned long long ua = *(unsigned long long*)&a;
    unsigned long long ub = *(unsigned long long*)&b;
    unsigned long long uc;
    asm("mul.rn.f32x2 %0, %1, %2;" : "=l"(uc) : "l"(ua), "l"(ub));
    return *(float2*)&uc;
}
__device__ __forceinline__ float2 f32x2_add(float2 a, float2 b) {
    unsigned long long ua = *(unsigned long long*)&a;
    unsigned long long ub = *(unsigned long long*)&b;
    unsigned long long uc;
    asm("add.rn.f32x2 %0, %1, %2;" : "=l"(uc) : "l"(ua), "l"(ub));
    return *(float2*)&uc;
}

__global__ __launch_bounds__(BLOCK, 2)
void combined_loss_fused(const float* __restrict__ pred,
                         const int*  __restrict__ tgt,
                         float* __restrict__ out)
{
    float acc_int[NUM_CLASSES];
    float acc_den[NUM_CLASSES];
    #pragma unroll
    for (int c = 0; c < NUM_CLASSES; c++) { acc_int[c] = 0.f; acc_den[c] = 0.f; }
    float acc_ce_l2 = 0.f;                       // sum of log2(p_t)
    unsigned long long cntlo = 0ull, cnthi = 0ull;  // 5-bit packed class counts

    const int tid0   = blockIdx.x * BLOCK + threadIdx.x;
    const int stride = GRID * BLOCK;
    const float2 l2e2 = make_float2(LOG2E, LOG2E);

    for (int q = tid0; q < NPAIR; q += stride) {
        const int p  = q << 1;
        const int b  = p >> HW_SHIFT;
        const int hw = p & (HW - 1);
        const float* base = pred + (size_t)b * (NUM_CLASSES * HW) + hw;
        const int2 t2 = ((const int2*)tgt)[q];

        // exp + sum (no max-subtract: logits are O(1), exp safe in fp32)
        float2 ex[NUM_CLASSES];
        float2 s = make_float2(0.f, 0.f);
        #pragma unroll
        for (int c = 0; c < NUM_CLASSES; c++) {
            float2 v  = *(const float2*)(base + c * HW);
            float2 xm = f32x2_mul(v, l2e2);       // x * log2(e)
            ex[c].x = fex2(xm.x);
            ex[c].y = fex2(xm.y);
            s = f32x2_add(s, ex[c]);
        }
        const float2 inv = make_float2(frcp(s.x), frcp(s.y));

        // probs + dice stats; p_t falls out of the select chain
        float pt0 = 0.f, pt1 = 0.f;
        #pragma unroll
        for (int c = 0; c < NUM_CLASSES; c++) {
            const float2 pr = f32x2_mul(ex[c], inv);
            const bool h0 = (c == t2.x);
            const bool h1 = (c == t2.y);
            pt0 = h0 ? pr.x : pt0;
            pt1 = h1 ? pr.y : pt1;
            acc_int[c] += (h0 ? pr.x : 0.f) + (h1 ? pr.y : 0.f);
            acc_den[c] += pr.x + pr.y;
        }
        acc_ce_l2 += flg2(pt0) + flg2(pt1);

        // packed per-class counts (5-bit fields; <=28 pixels/thread < 31)
        {
            const int t0 = t2.x, t1 = t2.y;
            const bool hi0 = (t0 >= 12), hi1 = (t1 >= 12);
            const unsigned long long i0 = 1ull << (5 * (hi0 ? t0 - 12 : t0));
            const unsigned long long i1 = 1ull << (5 * (hi1 ? t1 - 12 : t1));
            if (hi0) cnthi += i0; else cntlo += i0;
            if (hi1) cnthi += i1; else cntlo += i1;
        }
    }

    // fold counts into denominator (sum_p + count)
    #pragma unroll
    for (int c = 0; c < 12; c++)
        acc_den[c] += (float)((cntlo >> (5 * c)) & 31ull);
    #pragma unroll
    for (int c = 12; c < NUM_CLASSES; c++)
        acc_den[c] += (float)((cnthi >> (5 * (c - 12))) & 31ull);

    // deterministic block reduction
    __shared__ float s_part[NVALS][NWARPS];
    const int lane = threadIdx.x & 31;
    const int warp = threadIdx.x >> 5;

    #pragma unroll
    for (int c = 0; c < NUM_CLASSES; c++) {
        float v = warp_sum(acc_int[c]);
        if (lane == 0) s_part[c][warp] = v;
    }
    #pragma unroll
    for (int c = 0; c < NUM_CLASSES; c++) {
        float v = warp_sum(acc_den[c]);
        if (lane == 0) s_part[NUM_CLASSES + c][warp] = v;
    }
    {
        float v = warp_sum(acc_ce_l2);
        if (lane == 0) s_part[2 * NUM_CLASSES][warp] = v;
    }
    __syncthreads();

    if (threadIdx.x < NVALS) {
        float v = 0.f;
        #pragma unroll
        for (int w = 0; w < NWARPS; w++) v += s_part[threadIdx.x][w];
        g_scratch[threadIdx.x * GRID + blockIdx.x] = v;
    }

    // last-block final reduction (fixed order -> deterministic)
    __shared__ bool is_last;
    __threadfence();
    if (threadIdx.x == 0) {
        unsigned int v = atomicAdd(&g_count, 1u);
        is_last = (v == GRID - 1);
        if (is_last) g_count = 0u;
    }
    __syncthreads();
    if (!is_last) return;

    __shared__ float finals[NVALS];
    for (int v = warp; v < NVALS; v += NWARPS) {
        float s = 0.f;
        for (int bk = lane; bk < GRID; bk += 32)
            s += __ldcg(&g_scratch[v * GRID + bk]);
        s = warp_sum(s);
        if (lane == 0) finals[v] = s;
    }
    __syncthreads();

    if (threadIdx.x == 0) {
        float dl = 0.f;
        #pragma unroll
        for (int c = 0; c < NUM_CLASSES; c++) {
            const float inter = finals[c];
            const float den   = finals[NUM_CLASSES + c];
            dl += 1.0f - (2.0f * inter + SMOOTH) / (den + SMOOTH);
        }
        dl *= (1.0f / NUM_CLASSES);
        const float ce = -finals[2 * NUM_CLASSES] * LN2 * (1.0f / (float)NPIX);
        out[0] = 0.5f * dl + 0.5f * ce;
    }
}

extern "C" void kernel_launch(void* const* d_in, const int* in_sizes, int n_in,
                              void* d_out, int out_size)
{
    const float* pred = (const float*)d_in[0];
    const int*   tgt  = (const int*)d_in[1];
    float*       out  = (float*)d_out;
    (void)in_sizes; (void)n_in; (void)out_size;

    combined_loss_fused<<<GRID, BLOCK>>>(pred, tgt, out);
}